// round 10
// baseline (speedup 1.0000x reference)
#include <cuda_runtime.h>
#include <cstdint>

#define HH 1024
#define WW 1024
#define HWs (HH*WW)
#define BIGV 1e9f
#define L2E 1.4426950408889634f

#define XW 71          // x window: [X0-3, X0+67]
#define PSTR 12        // floats per pixel slot (8 ch + 4 pad -> 48B, 16B aligned for LDS.128)
#define RSTR (XW*PSTR) // floats per row

typedef unsigned long long ull;

__device__ __forceinline__ ull pk(float a, float b) {
    ull r;
    asm("mov.b64 %0, {%1, %2};" : "=l"(r) : "f"(a), "f"(b));
    return r;
}
__device__ __forceinline__ void upk(ull v, float& a, float& b) {
    asm("mov.b64 {%0, %1}, %2;" : "=f"(a), "=f"(b) : "l"(v));
}
__device__ __forceinline__ ull fma2(ull a, ull b, ull c) {
    ull d;
    asm("fma.rn.f32x2 %0, %1, %2, %3;" : "=l"(d) : "l"(a), "l"(b), "l"(c));
    return d;
}
__device__ __forceinline__ float ex2(float x) {
    float y;
    asm("ex2.approx.f32 %0, %1;" : "=f"(y) : "f"(x));
    return y;
}
__device__ __forceinline__ float frcp(float x) {
    float y;
    asm("rcp.approx.f32 %0, %1;" : "=f"(y) : "f"(x));
    return y;
}

// Tile 64 wide x 8 tall. Block (64,4); thread (tx,ty) owns pixels
// (X0+tx, Y0+2ty) and (X0+tx, Y0+2ty+1) — vertically adjacent; each loaded
// neighbor value serves BOTH pixels. SMEM channel-interleaved, 48B pixel slot,
// channels fetched by TWO LDS.128 (conflict-free at stride-12 words).
// Rows rr=0 / rr=7 peeled (no masked-out chain work); {acc2, wsum} packed.
// R10: occupancy 3 -> 4 CTAs/SM (64-reg cap) to lift fma-pipe duty.
__global__ __launch_bounds__(256, 4)
void bilateral_kernel(const float* __restrict__ in, float* __restrict__ out)
{
    __shared__ float smf[14 * RSTR];   // 47712 B (x4 CTAs = 190.8 KB/SM)
    const int tx = threadIdx.x, ty = threadIdx.y;
    const int X0 = blockIdx.x * 64;
    const int Y0 = blockIdx.y * 8;
    const int b  = blockIdx.z;
    const float* __restrict__ inb = in + (size_t)b * 18 * HWs;

    // ---- fill channel-interleaved SMEM (+halo), sentinel for OOB ----
    const int tid = ty * 64 + tx;
    for (int i = tid; i < 14 * XW; i += 256) {
        int r = i / XW;
        int x = i - r * XW;
        int gy = Y0 - 3 + r;
        int gx = X0 - 3 + x;
        bool ok = ((unsigned)gx < WW) & ((unsigned)gy < HH);
        const float* g = inb + (size_t)gy * WW + gx;
        float4 u0, u1;
        u0.x = ok ? g[0 * HWs] : BIGV;
        u0.y = ok ? g[1 * HWs] : BIGV;
        u0.z = ok ? g[2 * HWs] : BIGV;
        u0.w = ok ? g[3 * HWs] : BIGV;
        u1.x = ok ? g[4 * HWs] : BIGV;
        u1.y = ok ? g[5 * HWs] : BIGV;
        u1.z = ok ? g[6 * HWs] : BIGV;
        u1.w = ok ? g[7 * HWs] : BIGV;
        float4* d = (float4*)&smf[r * RSTR + x * PSTR];
        d[0] = u0;
        d[1] = u1;
    }
    __syncthreads();

    const int gx = X0 + tx;
    const int ya = Y0 + 2 * ty;      // pixel a; pixel b = ya + 1

    // ---- per-pixel precompute: rp' = -(p^2)*log2(e), u = -2 rp' f, v = sum rp' f^2 ----
    ull rppA[4], rppB[4], upA[4], upB[4];
    float va = 0.f, vb = 0.f;
    const float* __restrict__ pa = inb + 8 * HWs + (size_t)ya * WW + gx;
    const float* __restrict__ pbp = pa + WW;
    const float* __restrict__ ca = &smf[(2 * ty + 3) * RSTR + (tx + 3) * PSTR];
    const float* __restrict__ cb = ca + RSTR;
    #pragma unroll
    for (int k = 0; k < 4; k++) {
        float p0a = pa[(2*k) * HWs],  p1a = pa[(2*k+1) * HWs];
        float p0b = pbp[(2*k) * HWs], p1b = pbp[(2*k+1) * HWs];
        float r0a = -(p0a * p0a) * L2E, r1a = -(p1a * p1a) * L2E;
        float r0b = -(p0b * p0b) * L2E, r1b = -(p1b * p1b) * L2E;
        float f0a = ca[2*k], f1a = ca[2*k+1];
        float f0b = cb[2*k], f1b = cb[2*k+1];
        va = fmaf(r0a * f0a, f0a, va); va = fmaf(r1a * f1a, f1a, va);
        vb = fmaf(r0b * f0b, f0b, vb); vb = fmaf(r1b * f1b, f1b, vb);
        rppA[k] = pk(r0a, r1a);
        rppB[k] = pk(r0b, r1b);
        upA[k]  = pk(-2.f * r0a * f0a, -2.f * r1a * f1a);
        upB[k]  = pk(-2.f * r0b * f0b, -2.f * r1b * f1b);
    }
    float qa, qb;
    qa = pa[8 * HWs];  qb = pbp[8 * HWs];
    const float sxa = -(qa * qa) * L2E, sxb = -(qb * qb) * L2E;
    qa = pa[9 * HWs];  qb = pbp[9 * HWs];
    const float sya = -(qa * qa) * L2E, syb = -(qb * qb) * L2E;

    ull acc01a = 0ULL, acc01b = 0ULL;
    ull acc2wsa = 0ULL, acc2wsb = 0ULL;   // packed {acc2, wsum}
    const float onef = 1.0f;

    // chain macro: 8-deep packed logw chain for one pixel
    #define CHAIN(RPP, UP, LW)                                   \
        { ull s_;                                                \
          s_ = fma2(RPP[0], f01, UP[0]); LW = fma2(s_, f01, LW); \
          s_ = fma2(RPP[1], f23, UP[1]); LW = fma2(s_, f23, LW); \
          s_ = fma2(RPP[2], f45, UP[2]); LW = fma2(s_, f45, LW); \
          s_ = fma2(RPP[3], f67, UP[3]); LW = fma2(s_, f67, LW); }

    // ---- peeled row rr=0: pixel a only (dy = -3) ----
    {
        const float rba = fmaf(sya, 9.f, va);
        const float* __restrict__ rowp = &smf[(2 * ty) * RSTR + tx * PSTR];
        #pragma unroll
        for (int dx = 0; dx < 7; dx++) {
            const float ddv = (float)((dx - 3) * (dx - 3));
            float ba = (dx == 3) ? rba : fmaf(sxa, ddv, rba);
            const ulonglong2* __restrict__ p = (const ulonglong2*)(rowp + dx * PSTR);
            ulonglong2 q0 = p[0], q1 = p[1];
            ull f01 = q0.x, f23 = q0.y, f45 = q1.x, f67 = q1.y;
            ull lwa = pk(ba, 0.f);
            CHAIN(rppA, upA, lwa);
            float ea, oa;
            upk(lwa, ea, oa);
            float wa = ex2(ea + oa);
            ull wwa = pk(wa, wa);
            float f2, f3u;
            upk(f23, f2, f3u);
            ull pf21 = pk(f2, onef);
            acc01a  = fma2(wwa, f01,  acc01a);
            acc2wsa = fma2(wwa, pf21, acc2wsa);
        }
    }

    // ---- main rows rr=1..6: both pixels, no masking ----
    for (int rr = 1; rr < 7; rr++) {
        int r = 2 * ty + rr;
        float da = (float)(rr - 3), db = (float)(rr - 4);
        float rba = fmaf(sya, da * da, va);
        float rbb = fmaf(syb, db * db, vb);
        const float* __restrict__ rowp = &smf[r * RSTR + tx * PSTR];
        #pragma unroll
        for (int dx = 0; dx < 7; dx++) {
            const float ddv = (float)((dx - 3) * (dx - 3));
            float ba = (dx == 3) ? rba : fmaf(sxa, ddv, rba);
            float bb = (dx == 3) ? rbb : fmaf(sxb, ddv, rbb);
            const ulonglong2* __restrict__ p = (const ulonglong2*)(rowp + dx * PSTR);
            ulonglong2 q0 = p[0], q1 = p[1];
            ull f01 = q0.x, f23 = q0.y, f45 = q1.x, f67 = q1.y;

            ull lwa = pk(ba, 0.f);
            ull lwb = pk(bb, 0.f);
            {
                ull s;
                s = fma2(rppA[0], f01, upA[0]); lwa = fma2(s, f01, lwa);
                s = fma2(rppB[0], f01, upB[0]); lwb = fma2(s, f01, lwb);
                s = fma2(rppA[1], f23, upA[1]); lwa = fma2(s, f23, lwa);
                s = fma2(rppB[1], f23, upB[1]); lwb = fma2(s, f23, lwb);
                s = fma2(rppA[2], f45, upA[2]); lwa = fma2(s, f45, lwa);
                s = fma2(rppB[2], f45, upB[2]); lwb = fma2(s, f45, lwb);
                s = fma2(rppA[3], f67, upA[3]); lwa = fma2(s, f67, lwa);
                s = fma2(rppB[3], f67, upB[3]); lwb = fma2(s, f67, lwb);
            }
            float ea, oa, eb, ob2;
            upk(lwa, ea, oa);
            upk(lwb, eb, ob2);
            float wa = ex2(ea + oa);
            float wb = ex2(eb + ob2);
            ull wwa = pk(wa, wa);
            ull wwb = pk(wb, wb);
            float f2, f3u;
            upk(f23, f2, f3u);
            ull pf21 = pk(f2, onef);
            acc01a  = fma2(wwa, f01,  acc01a);
            acc2wsa = fma2(wwa, pf21, acc2wsa);
            acc01b  = fma2(wwb, f01,  acc01b);
            acc2wsb = fma2(wwb, pf21, acc2wsb);
        }
    }

    // ---- peeled row rr=7: pixel b only (dy = +3) ----
    {
        const float rbb = fmaf(syb, 9.f, vb);
        const float* __restrict__ rowp = &smf[(2 * ty + 7) * RSTR + tx * PSTR];
        #pragma unroll
        for (int dx = 0; dx < 7; dx++) {
            const float ddv = (float)((dx - 3) * (dx - 3));
            float bb = (dx == 3) ? rbb : fmaf(sxb, ddv, rbb);
            const ulonglong2* __restrict__ p = (const ulonglong2*)(rowp + dx * PSTR);
            ulonglong2 q0 = p[0], q1 = p[1];
            ull f01 = q0.x, f23 = q0.y, f45 = q1.x, f67 = q1.y;
            ull lwb = pk(bb, 0.f);
            CHAIN(rppB, upB, lwb);
            float eb, ob2;
            upk(lwb, eb, ob2);
            float wb = ex2(eb + ob2);
            ull wwb = pk(wb, wb);
            float f2, f3u;
            upk(f23, f2, f3u);
            ull pf21 = pk(f2, onef);
            acc01b  = fma2(wwb, f01,  acc01b);
            acc2wsb = fma2(wwb, pf21, acc2wsb);
        }
    }
    #undef CHAIN

    float acc2a, wsa, acc2b, wsb, a0, a1;
    upk(acc2wsa, acc2a, wsa);
    upk(acc2wsb, acc2b, wsb);
    const float ia = frcp(wsa), ib = frcp(wsb);
    float* __restrict__ oa = out + (size_t)b * 3 * HWs + (size_t)ya * WW + gx;
    float* __restrict__ ob = oa + WW;
    upk(acc01a, a0, a1);
    oa[0]   = a0 * ia;  oa[HWs] = a1 * ia;  oa[2 * HWs] = acc2a * ia;
    upk(acc01b, a0, a1);
    ob[0]   = a0 * ib;  ob[HWs] = a1 * ib;  ob[2 * HWs] = acc2b * ib;
}

extern "C" void kernel_launch(void* const* d_in, const int* in_sizes, int n_in,
                              void* d_out, int out_size) {
    const float* in = (const float*)d_in[0];
    float* out = (float*)d_out;
    dim3 grid(WW / 64, HH / 8, 2);
    dim3 block(64, 4);
    bilateral_kernel<<<grid, block>>>(in, out);
}

// round 11
// speedup vs baseline: 1.0669x; 1.0669x over previous
#include <cuda_runtime.h>
#include <cstdint>

#define HH 1024
#define WW 1024
#define HWs (HH*WW)
#define BIGV 1e9f
#define L2E 1.4426950408889634f

#define XW 71          // x window: [X0-3, X0+67]
#define PSTR 12        // floats per pixel slot (8 ch + 4 pad -> 48B, 16B aligned for LDS.128)
#define RSTR (XW*PSTR) // floats per row

typedef unsigned long long ull;

__device__ __forceinline__ ull pk(float a, float b) {
    ull r;
    asm("mov.b64 %0, {%1, %2};" : "=l"(r) : "f"(a), "f"(b));
    return r;
}
__device__ __forceinline__ void upk(ull v, float& a, float& b) {
    asm("mov.b64 {%0, %1}, %2;" : "=f"(a), "=f"(b) : "l"(v));
}
__device__ __forceinline__ ull fma2(ull a, ull b, ull c) {
    ull d;
    asm("fma.rn.f32x2 %0, %1, %2, %3;" : "=l"(d) : "l"(a), "l"(b), "l"(c));
    return d;
}
__device__ __forceinline__ float ex2(float x) {
    float y;
    asm("ex2.approx.f32 %0, %1;" : "=f"(y) : "f"(x));
    return y;
}
__device__ __forceinline__ float frcp(float x) {
    float y;
    asm("rcp.approx.f32 %0, %1;" : "=f"(y) : "f"(x));
    return y;
}

// Tile 64 wide x 8 tall. Block (64,4); thread (tx,ty) owns pixels
// (X0+tx, Y0+2ty) and (X0+tx, Y0+2ty+1) — vertically adjacent; each loaded
// neighbor value serves BOTH pixels. SMEM channel-interleaved, 48B pixel slot,
// channels fetched by TWO LDS.128 (conflict-free at stride-12 words).
// Rows rr=0 / rr=7 peeled (no masked-out chain work); {acc2, wsum} packed.
// R11: spatial bases hoisted per-row as scalars; param LDGs hoisted above the
// fill barrier. Back to 3 CTAs/SM (R10 showed 64-reg spills lose).
__global__ __launch_bounds__(256, 3)
void bilateral_kernel(const float* __restrict__ in, float* __restrict__ out)
{
    __shared__ float smf[14 * RSTR];   // 47712 B
    const int tx = threadIdx.x, ty = threadIdx.y;
    const int X0 = blockIdx.x * 64;
    const int Y0 = blockIdx.y * 8;
    const int b  = blockIdx.z;
    const float* __restrict__ inb = in + (size_t)b * 18 * HWs;

    const int gx = X0 + tx;
    const int ya = Y0 + 2 * ty;      // pixel a; pixel b = ya + 1

    // ---- hoisted param loads (overlap their latency with the fill + barrier) ----
    const float* __restrict__ pa = inb + 8 * HWs + (size_t)ya * WW + gx;
    const float* __restrict__ pbp = pa + WW;
    float prA[10], prB[10];
    #pragma unroll
    for (int c = 0; c < 10; c++) {
        prA[c] = pa[c * HWs];
        prB[c] = pbp[c * HWs];
    }

    // ---- fill channel-interleaved SMEM (+halo), sentinel for OOB ----
    const int tid = ty * 64 + tx;
    for (int i = tid; i < 14 * XW; i += 256) {
        int r = i / XW;
        int x = i - r * XW;
        int gy = Y0 - 3 + r;
        int gxx = X0 - 3 + x;
        bool ok = ((unsigned)gxx < WW) & ((unsigned)gy < HH);
        const float* g = inb + (size_t)gy * WW + gxx;
        float4 u0, u1;
        u0.x = ok ? g[0 * HWs] : BIGV;
        u0.y = ok ? g[1 * HWs] : BIGV;
        u0.z = ok ? g[2 * HWs] : BIGV;
        u0.w = ok ? g[3 * HWs] : BIGV;
        u1.x = ok ? g[4 * HWs] : BIGV;
        u1.y = ok ? g[5 * HWs] : BIGV;
        u1.z = ok ? g[6 * HWs] : BIGV;
        u1.w = ok ? g[7 * HWs] : BIGV;
        float4* d = (float4*)&smf[r * RSTR + x * PSTR];
        d[0] = u0;
        d[1] = u1;
    }
    __syncthreads();

    // ---- per-pixel precompute: rp' = -(p^2)*log2(e), u = -2 rp' f, v = sum rp' f^2 ----
    ull rppA[4], rppB[4], upA[4], upB[4];
    float va = 0.f, vb = 0.f;
    const float* __restrict__ ca = &smf[(2 * ty + 3) * RSTR + (tx + 3) * PSTR];
    const float* __restrict__ cb = ca + RSTR;
    #pragma unroll
    for (int k = 0; k < 4; k++) {
        float r0a = -(prA[2*k]   * prA[2*k])   * L2E;
        float r1a = -(prA[2*k+1] * prA[2*k+1]) * L2E;
        float r0b = -(prB[2*k]   * prB[2*k])   * L2E;
        float r1b = -(prB[2*k+1] * prB[2*k+1]) * L2E;
        float f0a = ca[2*k], f1a = ca[2*k+1];
        float f0b = cb[2*k], f1b = cb[2*k+1];
        va = fmaf(r0a * f0a, f0a, va); va = fmaf(r1a * f1a, f1a, va);
        vb = fmaf(r0b * f0b, f0b, vb); vb = fmaf(r1b * f1b, f1b, vb);
        rppA[k] = pk(r0a, r1a);
        rppB[k] = pk(r0b, r1b);
        upA[k]  = pk(-2.f * r0a * f0a, -2.f * r1a * f1a);
        upB[k]  = pk(-2.f * r0b * f0b, -2.f * r1b * f1b);
    }
    const float sxa = -(prA[8] * prA[8]) * L2E, sxb = -(prB[8] * prB[8]) * L2E;
    const float sya = -(prA[9] * prA[9]) * L2E, syb = -(prB[9] * prB[9]) * L2E;

    ull acc01a = 0ULL, acc01b = 0ULL;
    ull acc2wsa = 0ULL, acc2wsb = 0ULL;   // packed {acc2, wsum}
    const float onef = 1.0f;

    // chain macro: 8-deep packed logw chain for one pixel
    #define CHAIN(RPP, UP, LW)                                   \
        { ull s_;                                                \
          s_ = fma2(RPP[0], f01, UP[0]); LW = fma2(s_, f01, LW); \
          s_ = fma2(RPP[1], f23, UP[1]); LW = fma2(s_, f23, LW); \
          s_ = fma2(RPP[2], f45, UP[2]); LW = fma2(s_, f45, LW); \
          s_ = fma2(RPP[3], f67, UP[3]); LW = fma2(s_, f67, LW); }
    // |dx-3| -> base index: 3,2,1,0,1,2,3
    #define BIDX(dx) ((dx) < 3 ? (3 - (dx)) : ((dx) - 3))

    // ---- peeled row rr=0: pixel a only (dy = -3) ----
    {
        const float rba = fmaf(sya, 9.f, va);
        float bA[4];
        bA[0] = rba;
        bA[1] = fmaf(sxa, 1.f, rba);
        bA[2] = fmaf(sxa, 4.f, rba);
        bA[3] = fmaf(sxa, 9.f, rba);
        const float* __restrict__ rowp = &smf[(2 * ty) * RSTR + tx * PSTR];
        #pragma unroll
        for (int dx = 0; dx < 7; dx++) {
            const ulonglong2* __restrict__ p = (const ulonglong2*)(rowp + dx * PSTR);
            ulonglong2 q0 = p[0], q1 = p[1];
            ull f01 = q0.x, f23 = q0.y, f45 = q1.x, f67 = q1.y;
            ull lwa = pk(bA[BIDX(dx)], 0.f);
            CHAIN(rppA, upA, lwa);
            float ea, oa;
            upk(lwa, ea, oa);
            float wa = ex2(ea + oa);
            ull wwa = pk(wa, wa);
            float f2, f3u;
            upk(f23, f2, f3u);
            ull pf21 = pk(f2, onef);
            acc01a  = fma2(wwa, f01,  acc01a);
            acc2wsa = fma2(wwa, pf21, acc2wsa);
        }
    }

    // ---- main rows rr=1..6: both pixels, no masking ----
    for (int rr = 1; rr < 7; rr++) {
        int r = 2 * ty + rr;
        float da = (float)(rr - 3), db = (float)(rr - 4);
        float rba = fmaf(sya, da * da, va);
        float rbb = fmaf(syb, db * db, vb);
        float bA[4], bB[4];
        bA[0] = rba;                     bB[0] = rbb;
        bA[1] = fmaf(sxa, 1.f, rba);     bB[1] = fmaf(sxb, 1.f, rbb);
        bA[2] = fmaf(sxa, 4.f, rba);     bB[2] = fmaf(sxb, 4.f, rbb);
        bA[3] = fmaf(sxa, 9.f, rba);     bB[3] = fmaf(sxb, 9.f, rbb);
        const float* __restrict__ rowp = &smf[r * RSTR + tx * PSTR];
        #pragma unroll
        for (int dx = 0; dx < 7; dx++) {
            const ulonglong2* __restrict__ p = (const ulonglong2*)(rowp + dx * PSTR);
            ulonglong2 q0 = p[0], q1 = p[1];
            ull f01 = q0.x, f23 = q0.y, f45 = q1.x, f67 = q1.y;

            ull lwa = pk(bA[BIDX(dx)], 0.f);
            ull lwb = pk(bB[BIDX(dx)], 0.f);
            {
                ull s;
                s = fma2(rppA[0], f01, upA[0]); lwa = fma2(s, f01, lwa);
                s = fma2(rppB[0], f01, upB[0]); lwb = fma2(s, f01, lwb);
                s = fma2(rppA[1], f23, upA[1]); lwa = fma2(s, f23, lwa);
                s = fma2(rppB[1], f23, upB[1]); lwb = fma2(s, f23, lwb);
                s = fma2(rppA[2], f45, upA[2]); lwa = fma2(s, f45, lwa);
                s = fma2(rppB[2], f45, upB[2]); lwb = fma2(s, f45, lwb);
                s = fma2(rppA[3], f67, upA[3]); lwa = fma2(s, f67, lwa);
                s = fma2(rppB[3], f67, upB[3]); lwb = fma2(s, f67, lwb);
            }
            float ea, oa, eb, ob2;
            upk(lwa, ea, oa);
            upk(lwb, eb, ob2);
            float wa = ex2(ea + oa);
            float wb = ex2(eb + ob2);
            ull wwa = pk(wa, wa);
            ull wwb = pk(wb, wb);
            float f2, f3u;
            upk(f23, f2, f3u);
            ull pf21 = pk(f2, onef);
            acc01a  = fma2(wwa, f01,  acc01a);
            acc2wsa = fma2(wwa, pf21, acc2wsa);
            acc01b  = fma2(wwb, f01,  acc01b);
            acc2wsb = fma2(wwb, pf21, acc2wsb);
        }
    }

    // ---- peeled row rr=7: pixel b only (dy = +3) ----
    {
        const float rbb = fmaf(syb, 9.f, vb);
        float bB[4];
        bB[0] = rbb;
        bB[1] = fmaf(sxb, 1.f, rbb);
        bB[2] = fmaf(sxb, 4.f, rbb);
        bB[3] = fmaf(sxb, 9.f, rbb);
        const float* __restrict__ rowp = &smf[(2 * ty + 7) * RSTR + tx * PSTR];
        #pragma unroll
        for (int dx = 0; dx < 7; dx++) {
            const ulonglong2* __restrict__ p = (const ulonglong2*)(rowp + dx * PSTR);
            ulonglong2 q0 = p[0], q1 = p[1];
            ull f01 = q0.x, f23 = q0.y, f45 = q1.x, f67 = q1.y;
            ull lwb = pk(bB[BIDX(dx)], 0.f);
            CHAIN(rppB, upB, lwb);
            float eb, ob2;
            upk(lwb, eb, ob2);
            float wb = ex2(eb + ob2);
            ull wwb = pk(wb, wb);
            float f2, f3u;
            upk(f23, f2, f3u);
            ull pf21 = pk(f2, onef);
            acc01b  = fma2(wwb, f01,  acc01b);
            acc2wsb = fma2(wwb, pf21, acc2wsb);
        }
    }
    #undef CHAIN
    #undef BIDX

    float acc2a, wsa, acc2b, wsb, a0, a1;
    upk(acc2wsa, acc2a, wsa);
    upk(acc2wsb, acc2b, wsb);
    const float ia = frcp(wsa), ib = frcp(wsb);
    float* __restrict__ oa = out + (size_t)b * 3 * HWs + (size_t)ya * WW + gx;
    float* __restrict__ ob = oa + WW;
    upk(acc01a, a0, a1);
    oa[0]   = a0 * ia;  oa[HWs] = a1 * ia;  oa[2 * HWs] = acc2a * ia;
    upk(acc01b, a0, a1);
    ob[0]   = a0 * ib;  ob[HWs] = a1 * ib;  ob[2 * HWs] = acc2b * ib;
}

extern "C" void kernel_launch(void* const* d_in, const int* in_sizes, int n_in,
                              void* d_out, int out_size) {
    const float* in = (const float*)d_in[0];
    float* out = (float*)d_out;
    dim3 grid(WW / 64, HH / 8, 2);
    dim3 block(64, 4);
    bilateral_kernel<<<grid, block>>>(in, out);
}

// round 12
// speedup vs baseline: 1.0850x; 1.0169x over previous
#include <cuda_runtime.h>
#include <cstdint>

#define HH 1024
#define WW 1024
#define HWs (HH*WW)
#define BIGV 1e9f
#define L2E 1.4426950408889634f

#define XW 71          // x window: [X0-3, X0+67]
#define PSTR 12        // floats per pixel slot (8 ch + 4 pad -> 48B, 16B aligned for LDS.128)
#define RSTR (XW*PSTR) // floats per row

typedef unsigned long long ull;

__device__ __forceinline__ ull pk(float a, float b) {
    ull r;
    asm("mov.b64 %0, {%1, %2};" : "=l"(r) : "f"(a), "f"(b));
    return r;
}
__device__ __forceinline__ void upk(ull v, float& a, float& b) {
    asm("mov.b64 {%0, %1}, %2;" : "=f"(a), "=f"(b) : "l"(v));
}
__device__ __forceinline__ ull fma2(ull a, ull b, ull c) {
    ull d;
    asm("fma.rn.f32x2 %0, %1, %2, %3;" : "=l"(d) : "l"(a), "l"(b), "l"(c));
    return d;
}
__device__ __forceinline__ float ex2(float x) {
    float y;
    asm("ex2.approx.f32 %0, %1;" : "=f"(y) : "f"(x));
    return y;
}
__device__ __forceinline__ float frcp(float x) {
    float y;
    asm("rcp.approx.f32 %0, %1;" : "=f"(y) : "f"(x));
    return y;
}

// Tile 64 wide x 8 tall. Block (64,4); thread (tx,ty) owns pixels
// (X0+tx, Y0+2ty) and (X0+tx, Y0+2ty+1) — vertically adjacent; each loaded
// neighbor value serves BOTH pixels. SMEM channel-interleaved, 48B pixel slot,
// channels fetched by TWO LDS.128 (conflict-free at stride-12 words).
// Rows rr=0 / rr=7 peeled; per-row scalar spatial bases; params hoisted.
// R12: explicit one-iteration LDS rotation — next dx slot's loads issue before
// the current chain/exp/accumulate tail, hiding the 29-cyc LDS latency.
__global__ __launch_bounds__(256, 3)
void bilateral_kernel(const float* __restrict__ in, float* __restrict__ out)
{
    __shared__ float smf[14 * RSTR];   // 47712 B
    const int tx = threadIdx.x, ty = threadIdx.y;
    const int X0 = blockIdx.x * 64;
    const int Y0 = blockIdx.y * 8;
    const int b  = blockIdx.z;
    const float* __restrict__ inb = in + (size_t)b * 18 * HWs;

    const int gx = X0 + tx;
    const int ya = Y0 + 2 * ty;      // pixel a; pixel b = ya + 1

    // ---- hoisted param loads (overlap with fill + barrier) ----
    const float* __restrict__ pa = inb + 8 * HWs + (size_t)ya * WW + gx;
    const float* __restrict__ pbp = pa + WW;
    float prA[10], prB[10];
    #pragma unroll
    for (int c = 0; c < 10; c++) {
        prA[c] = pa[c * HWs];
        prB[c] = pbp[c * HWs];
    }

    // ---- fill channel-interleaved SMEM (+halo), sentinel for OOB ----
    const int tid = ty * 64 + tx;
    for (int i = tid; i < 14 * XW; i += 256) {
        int r = i / XW;
        int x = i - r * XW;
        int gy = Y0 - 3 + r;
        int gxx = X0 - 3 + x;
        bool ok = ((unsigned)gxx < WW) & ((unsigned)gy < HH);
        const float* g = inb + (size_t)gy * WW + gxx;
        float4 u0, u1;
        u0.x = ok ? g[0 * HWs] : BIGV;
        u0.y = ok ? g[1 * HWs] : BIGV;
        u0.z = ok ? g[2 * HWs] : BIGV;
        u0.w = ok ? g[3 * HWs] : BIGV;
        u1.x = ok ? g[4 * HWs] : BIGV;
        u1.y = ok ? g[5 * HWs] : BIGV;
        u1.z = ok ? g[6 * HWs] : BIGV;
        u1.w = ok ? g[7 * HWs] : BIGV;
        float4* d = (float4*)&smf[r * RSTR + x * PSTR];
        d[0] = u0;
        d[1] = u1;
    }
    __syncthreads();

    // ---- per-pixel precompute: rp' = -(p^2)*log2(e), u = -2 rp' f, v = sum rp' f^2 ----
    ull rppA[4], rppB[4], upA[4], upB[4];
    float va = 0.f, vb = 0.f;
    const float* __restrict__ ca = &smf[(2 * ty + 3) * RSTR + (tx + 3) * PSTR];
    const float* __restrict__ cb = ca + RSTR;
    #pragma unroll
    for (int k = 0; k < 4; k++) {
        float r0a = -(prA[2*k]   * prA[2*k])   * L2E;
        float r1a = -(prA[2*k+1] * prA[2*k+1]) * L2E;
        float r0b = -(prB[2*k]   * prB[2*k])   * L2E;
        float r1b = -(prB[2*k+1] * prB[2*k+1]) * L2E;
        float f0a = ca[2*k], f1a = ca[2*k+1];
        float f0b = cb[2*k], f1b = cb[2*k+1];
        va = fmaf(r0a * f0a, f0a, va); va = fmaf(r1a * f1a, f1a, va);
        vb = fmaf(r0b * f0b, f0b, vb); vb = fmaf(r1b * f1b, f1b, vb);
        rppA[k] = pk(r0a, r1a);
        rppB[k] = pk(r0b, r1b);
        upA[k]  = pk(-2.f * r0a * f0a, -2.f * r1a * f1a);
        upB[k]  = pk(-2.f * r0b * f0b, -2.f * r1b * f1b);
    }
    const float sxa = -(prA[8] * prA[8]) * L2E, sxb = -(prB[8] * prB[8]) * L2E;
    const float sya = -(prA[9] * prA[9]) * L2E, syb = -(prB[9] * prB[9]) * L2E;

    ull acc01a = 0ULL, acc01b = 0ULL;
    ull acc2wsa = 0ULL, acc2wsb = 0ULL;   // packed {acc2, wsum}
    const float onef = 1.0f;

    // load the 4 packed channel words of slot (rowp + dx*PSTR)
    #define LOADSLOT(ROWP, DX, A01, A23, A45, A67)                          \
        { const ulonglong2* p_ = (const ulonglong2*)((ROWP) + (DX) * PSTR); \
          ulonglong2 t0_ = p_[0], t1_ = p_[1];                              \
          A01 = t0_.x; A23 = t0_.y; A45 = t1_.x; A67 = t1_.y; }

    // 8-deep packed logw chain for one pixel
    #define CHAIN(RPP, UP, LW)                                   \
        { ull s_;                                                \
          s_ = fma2(RPP[0], f01, UP[0]); LW = fma2(s_, f01, LW); \
          s_ = fma2(RPP[1], f23, UP[1]); LW = fma2(s_, f23, LW); \
          s_ = fma2(RPP[2], f45, UP[2]); LW = fma2(s_, f45, LW); \
          s_ = fma2(RPP[3], f67, UP[3]); LW = fma2(s_, f67, LW); }
    // |dx-3| -> base index: 3,2,1,0,1,2,3
    #define BIDX(dx) ((dx) < 3 ? (3 - (dx)) : ((dx) - 3))

    // ---- peeled row rr=0: pixel a only (dy = -3) ----
    {
        const float rba = fmaf(sya, 9.f, va);
        float bA[4];
        bA[0] = rba;
        bA[1] = fmaf(sxa, 1.f, rba);
        bA[2] = fmaf(sxa, 4.f, rba);
        bA[3] = fmaf(sxa, 9.f, rba);
        const float* __restrict__ rowp = &smf[(2 * ty) * RSTR + tx * PSTR];
        ull nf01, nf23, nf45, nf67;
        LOADSLOT(rowp, 0, nf01, nf23, nf45, nf67);
        #pragma unroll
        for (int dx = 0; dx < 7; dx++) {
            ull f01 = nf01, f23 = nf23, f45 = nf45, f67 = nf67;
            if (dx < 6) LOADSLOT(rowp, dx + 1, nf01, nf23, nf45, nf67);
            ull lwa = pk(bA[BIDX(dx)], 0.f);
            CHAIN(rppA, upA, lwa);
            float ea, oa;
            upk(lwa, ea, oa);
            float wa = ex2(ea + oa);
            ull wwa = pk(wa, wa);
            float f2, f3u;
            upk(f23, f2, f3u);
            ull pf21 = pk(f2, onef);
            acc01a  = fma2(wwa, f01,  acc01a);
            acc2wsa = fma2(wwa, pf21, acc2wsa);
        }
    }

    // ---- main rows rr=1..6: both pixels, no masking ----
    for (int rr = 1; rr < 7; rr++) {
        int r = 2 * ty + rr;
        float da = (float)(rr - 3), db = (float)(rr - 4);
        float rba = fmaf(sya, da * da, va);
        float rbb = fmaf(syb, db * db, vb);
        float bA[4], bB[4];
        bA[0] = rba;                     bB[0] = rbb;
        bA[1] = fmaf(sxa, 1.f, rba);     bB[1] = fmaf(sxb, 1.f, rbb);
        bA[2] = fmaf(sxa, 4.f, rba);     bB[2] = fmaf(sxb, 4.f, rbb);
        bA[3] = fmaf(sxa, 9.f, rba);     bB[3] = fmaf(sxb, 9.f, rbb);
        const float* __restrict__ rowp = &smf[r * RSTR + tx * PSTR];
        ull nf01, nf23, nf45, nf67;
        LOADSLOT(rowp, 0, nf01, nf23, nf45, nf67);
        #pragma unroll
        for (int dx = 0; dx < 7; dx++) {
            ull f01 = nf01, f23 = nf23, f45 = nf45, f67 = nf67;
            if (dx < 6) LOADSLOT(rowp, dx + 1, nf01, nf23, nf45, nf67);

            ull lwa = pk(bA[BIDX(dx)], 0.f);
            ull lwb = pk(bB[BIDX(dx)], 0.f);
            {
                ull s;
                s = fma2(rppA[0], f01, upA[0]); lwa = fma2(s, f01, lwa);
                s = fma2(rppB[0], f01, upB[0]); lwb = fma2(s, f01, lwb);
                s = fma2(rppA[1], f23, upA[1]); lwa = fma2(s, f23, lwa);
                s = fma2(rppB[1], f23, upB[1]); lwb = fma2(s, f23, lwb);
                s = fma2(rppA[2], f45, upA[2]); lwa = fma2(s, f45, lwa);
                s = fma2(rppB[2], f45, upB[2]); lwb = fma2(s, f45, lwb);
                s = fma2(rppA[3], f67, upA[3]); lwa = fma2(s, f67, lwa);
                s = fma2(rppB[3], f67, upB[3]); lwb = fma2(s, f67, lwb);
            }
            float ea, oa, eb, ob2;
            upk(lwa, ea, oa);
            upk(lwb, eb, ob2);
            float wa = ex2(ea + oa);
            float wb = ex2(eb + ob2);
            ull wwa = pk(wa, wa);
            ull wwb = pk(wb, wb);
            float f2, f3u;
            upk(f23, f2, f3u);
            ull pf21 = pk(f2, onef);
            acc01a  = fma2(wwa, f01,  acc01a);
            acc2wsa = fma2(wwa, pf21, acc2wsa);
            acc01b  = fma2(wwb, f01,  acc01b);
            acc2wsb = fma2(wwb, pf21, acc2wsb);
        }
    }

    // ---- peeled row rr=7: pixel b only (dy = +3) ----
    {
        const float rbb = fmaf(syb, 9.f, vb);
        float bB[4];
        bB[0] = rbb;
        bB[1] = fmaf(sxb, 1.f, rbb);
        bB[2] = fmaf(sxb, 4.f, rbb);
        bB[3] = fmaf(sxb, 9.f, rbb);
        const float* __restrict__ rowp = &smf[(2 * ty + 7) * RSTR + tx * PSTR];
        ull nf01, nf23, nf45, nf67;
        LOADSLOT(rowp, 0, nf01, nf23, nf45, nf67);
        #pragma unroll
        for (int dx = 0; dx < 7; dx++) {
            ull f01 = nf01, f23 = nf23, f45 = nf45, f67 = nf67;
            if (dx < 6) LOADSLOT(rowp, dx + 1, nf01, nf23, nf45, nf67);
            ull lwb = pk(bB[BIDX(dx)], 0.f);
            CHAIN(rppB, upB, lwb);
            float eb, ob2;
            upk(lwb, eb, ob2);
            float wb = ex2(eb + ob2);
            ull wwb = pk(wb, wb);
            float f2, f3u;
            upk(f23, f2, f3u);
            ull pf21 = pk(f2, onef);
            acc01b  = fma2(wwb, f01,  acc01b);
            acc2wsb = fma2(wwb, pf21, acc2wsb);
        }
    }
    #undef CHAIN
    #undef BIDX
    #undef LOADSLOT

    float acc2a, wsa, acc2b, wsb, a0, a1;
    upk(acc2wsa, acc2a, wsa);
    upk(acc2wsb, acc2b, wsb);
    const float ia = frcp(wsa), ib = frcp(wsb);
    float* __restrict__ oa = out + (size_t)b * 3 * HWs + (size_t)ya * WW + gx;
    float* __restrict__ ob = oa + WW;
    upk(acc01a, a0, a1);
    oa[0]   = a0 * ia;  oa[HWs] = a1 * ia;  oa[2 * HWs] = acc2a * ia;
    upk(acc01b, a0, a1);
    ob[0]   = a0 * ib;  ob[HWs] = a1 * ib;  ob[2 * HWs] = acc2b * ib;
}

extern "C" void kernel_launch(void* const* d_in, const int* in_sizes, int n_in,
                              void* d_out, int out_size) {
    const float* in = (const float*)d_in[0];
    float* out = (float*)d_out;
    dim3 grid(WW / 64, HH / 8, 2);
    dim3 block(64, 4);
    bilateral_kernel<<<grid, block>>>(in, out);
}